// round 1
// baseline (speedup 1.0000x reference)
#include <cuda_runtime.h>
#include <cuda_bf16.h>

// ---------------------------------------------------------------------------
// MetaCNNLSTM: conv1d(64->256,k9,same) + GN(8)+ReLU -> 3x LSTM(512) -> mean -> head(50)
// B=32, T=512. All fp32. Recurrent part: persistent kernel + software grid barrier.
// ---------------------------------------------------------------------------

#define B_      32
#define CIN     64
#define T_      512
#define NF      256
#define KW      9
#define GN_G    8
#define H_      512
#define G4H     2048
#define NCLS    50

// ---- recurrent kernel geometry ----
#define LNB   128      // grid blocks (must be <= #SMs for sw barrier)
#define LNT   128      // threads per block
#define LJT   256      // j-columns per block tile
#define LCK   32       // k per chunk
#define LNJB  8        // j tiles   (8*256 = 2048)
#define LNKC  16       // k chunks  (16*32 = 512)

// ---- scratch (static __device__ — no allocations allowed) ----
__device__ float g_conv[B_ * NF * T_];              // (B,F,T)
__device__ float g_mu[B_ * GN_G];
__device__ float g_rs[B_ * GN_G];
__device__ float g_bufA[B_ * T_ * H_];              // layer in/out ping
__device__ float g_bufB[B_ * T_ * H_];              // layer in/out pong
__device__ float g_xg[T_ * B_ * G4H];               // (T,B,4H) gate preacts
__device__ float g_part[LNKC * B_ * G4H];           // split-k partials
__device__ float g_h[B_ * H_];
__device__ float g_c[B_ * H_];
__device__ unsigned g_bar_count;
__device__ unsigned g_gen;

// ---------------------------------------------------------------------------
// helpers
// ---------------------------------------------------------------------------
__device__ __forceinline__ float2 ffma2(float2 a, float2 b, float2 c) {
    float2 d;
    asm("fma.rn.f32x2 %0, %1, %2, %3;"
        : "=l"(*(unsigned long long*)&d)
        : "l"(*(unsigned long long*)&a),
          "l"(*(unsigned long long*)&b),
          "l"(*(unsigned long long*)&c));
    return d;
}

__device__ __forceinline__ float sigmoidf(float x) {
    return 1.0f / (1.0f + __expf(-x));
}
__device__ __forceinline__ float tanh_fast(float x) {
    // tanh(x) = 1 - 2/(1+e^{2x}); saturates correctly for |x| large
    return 1.0f - 2.0f / (1.0f + __expf(2.0f * x));
}

__device__ __forceinline__ void grid_barrier(unsigned nb) {
    __threadfence();
    __syncthreads();
    if (threadIdx.x == 0) {
        volatile unsigned* genp = &g_gen;
        unsigned my = *genp;
        unsigned a = atomicAdd(&g_bar_count, 1u);
        if (a == nb - 1u) {
            atomicExch(&g_bar_count, 0u);
            __threadfence();
            *genp = my + 1u;
        } else {
            while (*genp == my) { }
        }
    }
    __syncthreads();
}

// ---------------------------------------------------------------------------
// conv1d: out[b,f,t] = sum_{c,k} x[b,c,t+k-4]*w[f,c,k]
// ---------------------------------------------------------------------------
__global__ void conv_kernel(const float* __restrict__ x, const float* __restrict__ w) {
    int bf = blockIdx.x;              // B*NF blocks
    int b = bf >> 8, f = bf & 255;
    __shared__ float wsh[CIN * KW];
    for (int e = threadIdx.x; e < CIN * KW; e += blockDim.x)
        wsh[e] = w[f * CIN * KW + e];
    __syncthreads();
    const float* xb = x + b * CIN * T_;
    #pragma unroll
    for (int tt = 0; tt < 4; ++tt) {
        int t = tt * 128 + threadIdx.x;
        float acc = 0.f;
        for (int c = 0; c < CIN; ++c) {
            const float* xr = xb + c * T_;
            const float* wr = wsh + c * KW;
            #pragma unroll
            for (int k = 0; k < KW; ++k) {
                int ti = t + k - 4;
                if (ti >= 0 && ti < T_) acc += xr[ti] * wr[k];
            }
        }
        g_conv[(b * NF + f) * T_ + t] = acc;
    }
}

// ---------------------------------------------------------------------------
// GroupNorm stats: per (b,g) over 32 ch x 512 t
// ---------------------------------------------------------------------------
__global__ void gn_stats_kernel() {
    int bg = blockIdx.x;              // B*GN_G = 256 blocks
    int b = bg >> 3, g = bg & 7;
    const int CPG = NF / GN_G;        // 32
    const float* base = g_conv + (b * NF + g * CPG) * T_;
    float s = 0.f, ss = 0.f;
    for (int e = threadIdx.x; e < CPG * T_; e += blockDim.x) {
        float v = base[e];
        s += v; ss += v * v;
    }
    __shared__ float sh_s[256], sh_q[256];
    sh_s[threadIdx.x] = s; sh_q[threadIdx.x] = ss;
    __syncthreads();
    for (int st = 128; st > 0; st >>= 1) {
        if (threadIdx.x < st) {
            sh_s[threadIdx.x] += sh_s[threadIdx.x + st];
            sh_q[threadIdx.x] += sh_q[threadIdx.x + st];
        }
        __syncthreads();
    }
    if (threadIdx.x == 0) {
        float n = (float)(CPG * T_);
        float mu = sh_s[0] / n;
        float var = sh_q[0] / n - mu * mu;
        g_mu[bg] = mu;
        g_rs[bg] = rsqrtf(var + 1e-5f);
    }
}

// ---------------------------------------------------------------------------
// GN apply + ReLU + transpose (B,F,T) -> (B,T,F) into g_bufA (Din=256 packed)
// ---------------------------------------------------------------------------
__global__ void gn_apply_kernel(const float* __restrict__ gamma, const float* __restrict__ beta) {
    int idx = blockIdx.x * blockDim.x + threadIdx.x;   // over B*NF*T_
    if (idx >= B_ * NF * T_) return;
    int t = idx & 511;
    int f = (idx >> 9) & 255;
    int b = idx >> 17;
    int g = f >> 5;
    float v = g_conv[idx];
    v = (v - g_mu[b * 8 + g]) * g_rs[b * 8 + g] * gamma[f] + beta[f];
    v = fmaxf(v, 0.f);
    g_bufA[(b * T_ + t) * NF + f] = v;
}

// ---------------------------------------------------------------------------
// input-projection SGEMM: xg[(t*32+b), n] = X[b,t,:] . Wih[n,:] + bias[n]
// 128x128x8 tiles, 8x8 per-thread, f32x2 FMA
// ---------------------------------------------------------------------------
__global__ __launch_bounds__(256) void xg_gemm_kernel(int layer,
                                                      const float* __restrict__ Wih,
                                                      const float* __restrict__ bias,
                                                      int Din) {
    const float* X = (layer == 1) ? g_bufA : ((layer == 2) ? g_bufB : g_bufA);
    __shared__ __align__(16) float As[8][128];
    __shared__ __align__(16) float Bs[8][128];

    int m0 = blockIdx.y * 128, n0 = blockIdx.x * 128;
    int tid = threadIdx.x;
    int tx = tid & 15, ty = tid >> 4;
    int lrow = tid >> 1;                 // 0..127
    int lcol = (tid & 1) * 4;            // 0 or 4

    // A-row global base (row m -> x[b][t][:])
    int m = m0 + lrow;
    int ab = m & 31, at = m >> 5;
    const float* arow_p = X + (size_t)(ab * T_ + at) * Din;
    const float* brow_p = Wih + (size_t)(n0 + lrow) * Din;

    float2 acc[8][4];
    #pragma unroll
    for (int i = 0; i < 8; ++i)
        #pragma unroll
        for (int j = 0; j < 4; ++j) acc[i][j] = make_float2(0.f, 0.f);

    for (int k0 = 0; k0 < Din; k0 += 8) {
        float4 av = *(const float4*)(arow_p + k0 + lcol);
        float4 bv = *(const float4*)(brow_p + k0 + lcol);
        As[lcol + 0][lrow] = av.x; As[lcol + 1][lrow] = av.y;
        As[lcol + 2][lrow] = av.z; As[lcol + 3][lrow] = av.w;
        Bs[lcol + 0][lrow] = bv.x; Bs[lcol + 1][lrow] = bv.y;
        Bs[lcol + 2][lrow] = bv.z; Bs[lcol + 3][lrow] = bv.w;
        __syncthreads();
        #pragma unroll
        for (int kk = 0; kk < 8; ++kk) {
            float a[8];
            #pragma unroll
            for (int vm = 0; vm < 8; ++vm) a[vm] = As[kk][ty * 8 + vm];
            float2 w2[4];
            #pragma unroll
            for (int u = 0; u < 4; ++u)
                w2[u] = *(const float2*)&Bs[kk][tx * 2 + 32 * u];
            #pragma unroll
            for (int vm = 0; vm < 8; ++vm) {
                float2 a2 = make_float2(a[vm], a[vm]);
                #pragma unroll
                for (int u = 0; u < 4; ++u)
                    acc[vm][u] = ffma2(a2, w2[u], acc[vm][u]);
            }
        }
        __syncthreads();
    }

    #pragma unroll
    for (int vm = 0; vm < 8; ++vm) {
        int mm = m0 + ty * 8 + vm;
        float* cp = g_xg + (size_t)mm * G4H;
        #pragma unroll
        for (int u = 0; u < 4; ++u) {
            int n = n0 + tx * 2 + 32 * u;
            float2 r = acc[vm][u];
            r.x += bias[n]; r.y += bias[n + 1];
            *(float2*)&cp[n] = r;
        }
    }
}

// ---------------------------------------------------------------------------
// persistent LSTM scan for one layer.
// grid = 128 blocks = 8 j-tiles x 16 k-chunks; Whh tile held in shared all steps.
// ---------------------------------------------------------------------------
__global__ __launch_bounds__(LNT, 1) void lstm_kernel(int layer, const float* __restrict__ Whh) {
    float* Y = (layer == 1) ? g_bufB : ((layer == 2) ? g_bufA : g_bufB);

    __shared__ __align__(16) float ws[LCK * LJT];   // [k][j]  32KB
    __shared__ float hs[LCK][33];                   // [k][b]

    int tid = threadIdx.x;
    int jb = blockIdx.x & (LNJB - 1);
    int kc = blockIdx.x >> 3;
    int j0 = jb * LJT, k0 = kc * LCK;

    // load W tile once: ws[k][jl] = Whh[j0+jl][k0+k]
    for (int e = tid; e < LJT * LCK; e += LNT) {
        int jl = e >> 5, k = e & 31;
        ws[k * LJT + jl] = Whh[(size_t)(j0 + jl) * H_ + k0 + k];
    }

    // zero h, c
    {
        int cell = blockIdx.x * LNT + tid;          // 0..16383
        g_h[cell] = 0.f;
        g_c[cell] = 0.f;
    }
    grid_barrier(LNB);

    int jg = tid & 31;
    int bg = tid >> 5;
    int bbase = bg * 8;

    for (int t = 0; t < T_; ++t) {
        // load h chunk transposed: hs[k][b] = h[b][k0+k]
        for (int e = tid; e < B_ * LCK; e += LNT) {
            int b = e >> 5, k = e & 31;
            hs[k][b] = g_h[b * H_ + k0 + k];
        }
        __syncthreads();

        float2 acc[8][4];
        #pragma unroll
        for (int v = 0; v < 8; ++v)
            #pragma unroll
            for (int u = 0; u < 4; ++u) acc[v][u] = make_float2(0.f, 0.f);

        #pragma unroll 8
        for (int k = 0; k < LCK; ++k) {
            float hv[8];
            #pragma unroll
            for (int v = 0; v < 8; ++v) hv[v] = hs[k][bbase + v];
            float2 wv[4];
            #pragma unroll
            for (int u = 0; u < 4; ++u)
                wv[u] = *(const float2*)&ws[k * LJT + jg * 2 + 64 * u];
            #pragma unroll
            for (int v = 0; v < 8; ++v) {
                float2 h2 = make_float2(hv[v], hv[v]);
                #pragma unroll
                for (int u = 0; u < 4; ++u)
                    acc[v][u] = ffma2(h2, wv[u], acc[v][u]);
            }
        }

        // store partials
        #pragma unroll
        for (int v = 0; v < 8; ++v) {
            int b = bbase + v;
            float* pp = g_part + (size_t)(kc * B_ + b) * G4H + j0 + jg * 2;
            #pragma unroll
            for (int u = 0; u < 4; ++u)
                *(float2*)&pp[64 * u] = acc[v][u];
        }
        grid_barrier(LNB);

        // phase 2: reduce partials + xg, apply activations, update h/c
        {
            int cell = blockIdx.x * LNT + tid;     // (b,hidx)
            int b = cell >> 9, hh = cell & 511;
            const float* xgp = g_xg + (size_t)(t * B_ + b) * G4H;
            float gi = xgp[hh];
            float gf = xgp[512 + hh];
            float gg = xgp[1024 + hh];
            float go = xgp[1536 + hh];
            #pragma unroll
            for (int q = 0; q < LNKC; ++q) {
                const float* pp = g_part + (size_t)(q * B_ + b) * G4H;
                gi += pp[hh];
                gf += pp[512 + hh];
                gg += pp[1024 + hh];
                go += pp[1536 + hh];
            }
            float iv = sigmoidf(gi);
            float fv = sigmoidf(gf);
            float gv = tanh_fast(gg);
            float ov = sigmoidf(go);
            float c = fv * g_c[cell] + iv * gv;
            float h = ov * tanh_fast(c);
            g_c[cell] = c;
            g_h[cell] = h;
            Y[(size_t)(b * T_ + t) * H_ + hh] = h;
        }
        grid_barrier(LNB);
    }
}

// ---------------------------------------------------------------------------
// mean over T + head GEMV
// ---------------------------------------------------------------------------
__global__ void pool_head_kernel(const float* __restrict__ head_w,
                                 const float* __restrict__ head_b,
                                 float* __restrict__ out) {
    int b = blockIdx.x;
    int h = threadIdx.x;               // 512 threads
    __shared__ float feat[H_];
    const float* Y = g_bufB + (size_t)b * T_ * H_;
    float s = 0.f;
    for (int t = 0; t < T_; ++t) s += Y[t * H_ + h];
    feat[h] = s * (1.0f / (float)T_);
    __syncthreads();
    for (int c = threadIdx.x; c < NCLS; c += blockDim.x) {
        float a = head_b[c];
        const float* wr = head_w + c * H_;
        for (int k = 0; k < H_; ++k) a += feat[k] * wr[k];
        out[b * NCLS + c] = a;
    }
}

// ---------------------------------------------------------------------------
// launch
// ---------------------------------------------------------------------------
extern "C" void kernel_launch(void* const* d_in, const int* in_sizes, int n_in,
                              void* d_out, int out_size) {
    const float* x     = (const float*)d_in[0];
    const float* convw = (const float*)d_in[1];
    const float* gamma = (const float*)d_in[2];
    const float* beta  = (const float*)d_in[3];

    // input order can be dict order (head before lstm) or signature order
    bool head_first = (in_sizes[4] == NCLS * H_);
    int o = head_first ? 6 : 4;
    const float* headw = (const float*)d_in[head_first ? 4 : 13];
    const float* headb = (const float*)d_in[head_first ? 5 : 14];
    const float* wih[3] = { (const float*)d_in[o + 0], (const float*)d_in[o + 3], (const float*)d_in[o + 6] };
    const float* whh[3] = { (const float*)d_in[o + 1], (const float*)d_in[o + 4], (const float*)d_in[o + 7] };
    const float* bb[3]  = { (const float*)d_in[o + 2], (const float*)d_in[o + 5], (const float*)d_in[o + 8] };

    conv_kernel<<<B_ * NF, 128>>>(x, convw);
    gn_stats_kernel<<<B_ * GN_G, 256>>>();
    gn_apply_kernel<<<(B_ * NF * T_ + 255) / 256, 256>>>(gamma, beta);

    for (int layer = 1; layer <= 3; ++layer) {
        int din = (layer == 1) ? NF : H_;
        dim3 gg(G4H / 128, (B_ * T_) / 128);
        xg_gemm_kernel<<<gg, 256>>>(layer, wih[layer - 1], bb[layer - 1], din);
        lstm_kernel<<<LNB, LNT>>>(layer, whh[layer - 1]);
    }

    pool_head_kernel<<<B_, H_>>>(headw, headb, (float*)d_out);
}

// round 2
// speedup vs baseline: 1.3453x; 1.3453x over previous
#include <cuda_runtime.h>
#include <cuda_bf16.h>

// ---------------------------------------------------------------------------
// MetaCNNLSTM: conv1d(64->256,k9,same) + GN(8)+ReLU -> 3x LSTM(512) -> mean -> head(50)
// B=32, T=512, fp32.
// LSTM: persistent kernel, 128 blocks x 256 thr. Each block owns 4 cells
// (16 gate columns, full K=512). W tile smem-resident for all steps, c-state in
// registers, ONE grid barrier per step (acquire/release).
// ---------------------------------------------------------------------------

#define B_      32
#define CIN     64
#define T_      512
#define NF      256
#define KW      9
#define GN_G    8
#define H_      512
#define G4H     2048
#define NCLS    50

#define LNB     128            // persistent blocks (<= #SMs)
#define LNT     256

// smem layout (floats)
#define SM_HS    0             // hs[512][32]              16384
#define SM_W     16384         // wsm[16][521]              8336
#define SM_RED   24720         // red[8][16][44]            5632
#define SM_GS    30352         // gs[16][34]                 544
#define SM_XGS   30896         // xgs[4][32][4]              512
#define SM_HSM   31408         // hsm[32][4]                 128
#define SM_FLOATS 31536
#define SMEM_BYTES (SM_FLOATS * 4)

// ---- global scratch (no allocations allowed) ----
__device__ float g_conv[B_ * NF * T_];
__device__ float g_mu[B_ * GN_G];
__device__ float g_rs[B_ * GN_G];
__device__ float g_bufA[B_ * T_ * H_];
__device__ float g_bufB[B_ * T_ * H_];
__device__ float g_xg[T_ * B_ * G4H];          // [t][b][4H]
__device__ float g_h[H_ * B_];                 // [k][b]  (transposed!)
__device__ unsigned g_bar_count;
__device__ unsigned g_gen;

// ---------------------------------------------------------------------------
__device__ __forceinline__ float2 ffma2(float2 a, float2 b, float2 c) {
    float2 d;
    asm("fma.rn.f32x2 %0, %1, %2, %3;"
        : "=l"(*(unsigned long long*)&d)
        : "l"(*(unsigned long long*)&a),
          "l"(*(unsigned long long*)&b),
          "l"(*(unsigned long long*)&c));
    return d;
}
__device__ __forceinline__ float sigmoidf(float x) { return 1.0f / (1.0f + __expf(-x)); }
__device__ __forceinline__ float tanh_fast(float x) { return 1.0f - 2.0f / (1.0f + __expf(2.0f * x)); }

__device__ __forceinline__ unsigned ld_acquire(unsigned* p) {
    unsigned v;
    asm volatile("ld.acquire.gpu.global.u32 %0, [%1];" : "=r"(v) : "l"(p) : "memory");
    return v;
}
__device__ __forceinline__ void st_release(unsigned* p, unsigned v) {
    asm volatile("st.release.gpu.global.u32 [%0], %1;" :: "l"(p), "r"(v) : "memory");
}

__device__ __forceinline__ void gbar(unsigned& mygen) {
    __syncthreads();
    if (threadIdx.x == 0) {
        __threadfence();
        unsigned a = atomicAdd(&g_bar_count, 1u);
        if (a == LNB - 1u) { g_bar_count = 0u; st_release(&g_gen, mygen + 1u); }
        else { while (ld_acquire(&g_gen) == mygen) {} }
    }
    mygen++;
    __syncthreads();
}

// ---------------------------------------------------------------------------
// conv1d
// ---------------------------------------------------------------------------
__global__ void conv_kernel(const float* __restrict__ x, const float* __restrict__ w) {
    int bf = blockIdx.x;
    int b = bf >> 8, f = bf & 255;
    __shared__ float wsh[CIN * KW];
    for (int e = threadIdx.x; e < CIN * KW; e += blockDim.x)
        wsh[e] = w[f * CIN * KW + e];
    __syncthreads();
    const float* xb = x + b * CIN * T_;
    #pragma unroll
    for (int tt = 0; tt < 4; ++tt) {
        int t = tt * 128 + threadIdx.x;
        float acc = 0.f;
        for (int c = 0; c < CIN; ++c) {
            const float* xr = xb + c * T_;
            const float* wr = wsh + c * KW;
            #pragma unroll
            for (int k = 0; k < KW; ++k) {
                int ti = t + k - 4;
                if (ti >= 0 && ti < T_) acc += xr[ti] * wr[k];
            }
        }
        g_conv[(b * NF + f) * T_ + t] = acc;
    }
}

__global__ void gn_stats_kernel() {
    int bg = blockIdx.x;
    int b = bg >> 3, g = bg & 7;
    const int CPG = NF / GN_G;
    const float* base = g_conv + (b * NF + g * CPG) * T_;
    float s = 0.f, ss = 0.f;
    for (int e = threadIdx.x; e < CPG * T_; e += blockDim.x) {
        float v = base[e];
        s += v; ss += v * v;
    }
    __shared__ float sh_s[256], sh_q[256];
    sh_s[threadIdx.x] = s; sh_q[threadIdx.x] = ss;
    __syncthreads();
    for (int st = 128; st > 0; st >>= 1) {
        if (threadIdx.x < st) {
            sh_s[threadIdx.x] += sh_s[threadIdx.x + st];
            sh_q[threadIdx.x] += sh_q[threadIdx.x + st];
        }
        __syncthreads();
    }
    if (threadIdx.x == 0) {
        float n = (float)(CPG * T_);
        float mu = sh_s[0] / n;
        float var = sh_q[0] / n - mu * mu;
        g_mu[bg] = mu;
        g_rs[bg] = rsqrtf(var + 1e-5f);
    }
}

__global__ void gn_apply_kernel(const float* __restrict__ gamma, const float* __restrict__ beta) {
    int idx = blockIdx.x * blockDim.x + threadIdx.x;
    if (idx >= B_ * NF * T_) return;
    int t = idx & 511;
    int f = (idx >> 9) & 255;
    int b = idx >> 17;
    int g = f >> 5;
    float v = g_conv[idx];
    v = (v - g_mu[b * 8 + g]) * g_rs[b * 8 + g] * gamma[f] + beta[f];
    v = fmaxf(v, 0.f);
    g_bufA[(b * T_ + t) * NF + f] = v;
}

// ---------------------------------------------------------------------------
// input-projection SGEMM: xg[(t*32+b), n] = X[b,t,:] . Wih[n,:] + bias[n]
// ---------------------------------------------------------------------------
__global__ __launch_bounds__(256) void xg_gemm_kernel(int layer,
                                                      const float* __restrict__ Wih,
                                                      const float* __restrict__ bias,
                                                      int Din) {
    const float* X = (layer == 2) ? g_bufB : g_bufA;
    __shared__ __align__(16) float As[8][128];
    __shared__ __align__(16) float Bs[8][128];

    int m0 = blockIdx.y * 128, n0 = blockIdx.x * 128;
    int tid = threadIdx.x;
    int tx = tid & 15, ty = tid >> 4;
    int lrow = tid >> 1;
    int lcol = (tid & 1) * 4;

    int m = m0 + lrow;
    int ab = m & 31, at = m >> 5;
    const float* arow_p = X + (size_t)(ab * T_ + at) * Din;
    const float* brow_p = Wih + (size_t)(n0 + lrow) * Din;

    float2 acc[8][4];
    #pragma unroll
    for (int i = 0; i < 8; ++i)
        #pragma unroll
        for (int j = 0; j < 4; ++j) acc[i][j] = make_float2(0.f, 0.f);

    for (int k0 = 0; k0 < Din; k0 += 8) {
        float4 av = *(const float4*)(arow_p + k0 + lcol);
        float4 bv = *(const float4*)(brow_p + k0 + lcol);
        As[lcol + 0][lrow] = av.x; As[lcol + 1][lrow] = av.y;
        As[lcol + 2][lrow] = av.z; As[lcol + 3][lrow] = av.w;
        Bs[lcol + 0][lrow] = bv.x; Bs[lcol + 1][lrow] = bv.y;
        Bs[lcol + 2][lrow] = bv.z; Bs[lcol + 3][lrow] = bv.w;
        __syncthreads();
        #pragma unroll
        for (int kk = 0; kk < 8; ++kk) {
            float a[8];
            #pragma unroll
            for (int vm = 0; vm < 8; ++vm) a[vm] = As[kk][ty * 8 + vm];
            float2 w2[4];
            #pragma unroll
            for (int u = 0; u < 4; ++u)
                w2[u] = *(const float2*)&Bs[kk][tx * 2 + 32 * u];
            #pragma unroll
            for (int vm = 0; vm < 8; ++vm) {
                float2 a2 = make_float2(a[vm], a[vm]);
                #pragma unroll
                for (int u = 0; u < 4; ++u)
                    acc[vm][u] = ffma2(a2, w2[u], acc[vm][u]);
            }
        }
        __syncthreads();
    }

    #pragma unroll
    for (int vm = 0; vm < 8; ++vm) {
        int mm = m0 + ty * 8 + vm;
        float* cp = g_xg + (size_t)mm * G4H;
        #pragma unroll
        for (int u = 0; u < 4; ++u) {
            int n = n0 + tx * 2 + 32 * u;
            float2 r = acc[vm][u];
            r.x += bias[n]; r.y += bias[n + 1];
            *(float2*)&cp[n] = r;
        }
    }
}

// ---------------------------------------------------------------------------
// persistent LSTM scan: 128 blocks, block bx owns cells [bx*4, bx*4+4)
// (16 gate columns j = g*512 + c0 + cl, full K), one grid barrier per step.
// ---------------------------------------------------------------------------
__global__ __launch_bounds__(LNT, 1) void lstm_kernel(const float* __restrict__ Whh,
                                                      const float* __restrict__ xg,
                                                      float* __restrict__ Y) {
    extern __shared__ float sm[];
    float* hs  = sm + SM_HS;
    float* wsm = sm + SM_W;
    float* red = sm + SM_RED;
    float* gs  = sm + SM_GS;
    float* xgs = sm + SM_XGS;
    float* hsm = sm + SM_HSM;

    const int tid = threadIdx.x;
    const int bx = blockIdx.x;
    const int c0 = bx * 4;
    const int warp = tid >> 5, lane = tid & 31;
    const int kc = warp;            // 0..7 (k chunk of 64)
    const int jl = lane & 15;       // 0..15 (gate column within block)
    const int bh = lane >> 4;       // 0..1  (batch half)

    unsigned mygen = *((volatile unsigned*)&g_gen);

    // load W tile (16 j x 512 k) into smem, rows padded to 521 floats
    for (int e = tid; e < 16 * 128; e += LNT) {
        int j = e >> 7, k4 = e & 127;
        int jg = (j >> 2) * 512 + c0 + (j & 3);
        float4 v = *(const float4*)(Whh + (size_t)jg * H_ + k4 * 4);
        float* dst = wsm + j * 521 + k4 * 4;
        dst[0] = v.x; dst[1] = v.y; dst[2] = v.z; dst[3] = v.w;
    }
    // zero h
    if (tid < 128) g_h[bx * 128 + tid] = 0.f;
    gbar(mygen);

    float creg = 0.f;   // c-state (valid for tid<128: cl=tid>>5, b=tid&31)
    const float* wrow = wsm + jl * 521 + kc * 64;
    const float* hbase = hs + kc * 64 * 32 + bh * 16;
    float* rrow = red + (kc * 16 + jl) * 44 + bh * 16;

    for (int t = 0; t < T_; ++t) {
        // 1. cooperative copy of h (g_h is [k][b] -> identical layout, no transpose)
        #pragma unroll
        for (int r = 0; r < 16; ++r) {
            int f4 = tid + r * 256;
            *(float4*)(hs + f4 * 4) = *(const float4*)(g_h + f4 * 4);
        }
        __syncthreads();

        // 2. GEMM: acc[b-pair] over 64 k, 1 j per thread, 16 b
        float2 acc[8];
        #pragma unroll
        for (int i = 0; i < 8; ++i) acc[i] = make_float2(0.f, 0.f);

        #pragma unroll 16
        for (int kk = 0; kk < 64; ++kk) {
            float wv = wrow[kk];
            float2 w2 = make_float2(wv, wv);
            const float4* hp = (const float4*)(hbase + kk * 32);
            float4 h0 = hp[0], h1 = hp[1], h2 = hp[2], h3 = hp[3];
            acc[0] = ffma2(w2, make_float2(h0.x, h0.y), acc[0]);
            acc[1] = ffma2(w2, make_float2(h0.z, h0.w), acc[1]);
            acc[2] = ffma2(w2, make_float2(h1.x, h1.y), acc[2]);
            acc[3] = ffma2(w2, make_float2(h1.z, h1.w), acc[3]);
            acc[4] = ffma2(w2, make_float2(h2.x, h2.y), acc[4]);
            acc[5] = ffma2(w2, make_float2(h2.z, h2.w), acc[5]);
            acc[6] = ffma2(w2, make_float2(h3.x, h3.y), acc[6]);
            acc[7] = ffma2(w2, make_float2(h3.z, h3.w), acc[7]);
        }

        // 3. store k-partials
        ((float4*)rrow)[0] = make_float4(acc[0].x, acc[0].y, acc[1].x, acc[1].y);
        ((float4*)rrow)[1] = make_float4(acc[2].x, acc[2].y, acc[3].x, acc[3].y);
        ((float4*)rrow)[2] = make_float4(acc[4].x, acc[4].y, acc[5].x, acc[5].y);
        ((float4*)rrow)[3] = make_float4(acc[6].x, acc[6].y, acc[7].x, acc[7].y);

        // 3b. overlap: upper half prefetches xg (4 floats per (b,gate))
        float4 xv = make_float4(0.f, 0.f, 0.f, 0.f);
        int xb = 0, xga = 0;
        if (tid >= 128) {
            int t2 = tid - 128;
            xb = t2 >> 2; xga = t2 & 3;
            xv = *(const float4*)(xg + ((size_t)t * 32 + xb) * G4H + xga * 512 + c0);
        }
        __syncthreads();

        // 4. reduce over 8 k-chunks: 2 gate-values per thread
        {
            int j = tid >> 4, b0 = (tid & 15) * 2;
            float2 s = make_float2(0.f, 0.f);
            #pragma unroll
            for (int q = 0; q < 8; ++q) {
                float2 v = *(const float2*)(red + (q * 16 + j) * 44 + b0);
                s.x += v.x; s.y += v.y;
            }
            *(float2*)(gs + j * 34 + b0) = s;
        }
        if (tid >= 128) *(float4*)(xgs + (xga * 32 + xb) * 4) = xv;
        __syncthreads();

        // 5. activations: tid<128 -> (cl, b) cell
        if (tid < 128) {
            int cl = tid >> 5, b = tid & 31;
            float gi = gs[(0 * 4 + cl) * 34 + b] + xgs[(0 * 32 + b) * 4 + cl];
            float gf = gs[(1 * 4 + cl) * 34 + b] + xgs[(1 * 32 + b) * 4 + cl];
            float gg = gs[(2 * 4 + cl) * 34 + b] + xgs[(2 * 32 + b) * 4 + cl];
            float go = gs[(3 * 4 + cl) * 34 + b] + xgs[(3 * 32 + b) * 4 + cl];
            float iv = sigmoidf(gi);
            float fv = sigmoidf(gf);
            float gv = tanh_fast(gg);
            float ov = sigmoidf(go);
            creg = fv * creg + iv * gv;
            float hv = ov * tanh_fast(creg);
            g_h[(c0 + cl) * 32 + b] = hv;
            hsm[b * 4 + cl] = hv;
        }
        __syncthreads();

        // 6. grid barrier (arrive, overlap Y write with the wait)
        if (tid == 0) {
            __threadfence();
            unsigned a = atomicAdd(&g_bar_count, 1u);
            if (a == LNB - 1u) { g_bar_count = 0u; st_release(&g_gen, mygen + 1u); }
        }
        if (tid < 32) {
            float4 hv4 = ((const float4*)hsm)[tid];
            *(float4*)(Y + ((size_t)tid * T_ + t) * H_ + c0) = hv4;
        }
        if (tid == 0) { while (ld_acquire(&g_gen) == mygen) {} }
        mygen++;
        __syncthreads();
    }
}

// ---------------------------------------------------------------------------
// mean over T + head GEMV
// ---------------------------------------------------------------------------
__global__ void pool_head_kernel(const float* __restrict__ head_w,
                                 const float* __restrict__ head_b,
                                 float* __restrict__ out) {
    int b = blockIdx.x;
    int h = threadIdx.x;
    __shared__ float feat[H_];
    const float* Yp = g_bufB + (size_t)b * T_ * H_;
    float s = 0.f;
    for (int t = 0; t < T_; ++t) s += Yp[t * H_ + h];
    feat[h] = s * (1.0f / (float)T_);
    __syncthreads();
    for (int c = threadIdx.x; c < NCLS; c += blockDim.x) {
        float a = head_b[c];
        const float* wr = head_w + c * H_;
        for (int k = 0; k < H_; ++k) a += feat[k] * wr[k];
        out[b * NCLS + c] = a;
    }
}

// ---------------------------------------------------------------------------
extern "C" void kernel_launch(void* const* d_in, const int* in_sizes, int n_in,
                              void* d_out, int out_size) {
    const float* x     = (const float*)d_in[0];
    const float* convw = (const float*)d_in[1];
    const float* gamma = (const float*)d_in[2];
    const float* beta  = (const float*)d_in[3];

    bool head_first = (in_sizes[4] == NCLS * H_);
    int o = head_first ? 6 : 4;
    const float* headw = (const float*)d_in[head_first ? 4 : 13];
    const float* headb = (const float*)d_in[head_first ? 5 : 14];
    const float* wih[3] = { (const float*)d_in[o + 0], (const float*)d_in[o + 3], (const float*)d_in[o + 6] };
    const float* whh[3] = { (const float*)d_in[o + 1], (const float*)d_in[o + 4], (const float*)d_in[o + 7] };
    const float* bb[3]  = { (const float*)d_in[o + 2], (const float*)d_in[o + 5], (const float*)d_in[o + 8] };

    static int smem_set = 0;
    if (!smem_set) {
        cudaFuncSetAttribute(lstm_kernel, cudaFuncAttributeMaxDynamicSharedMemorySize, SMEM_BYTES);
        smem_set = 1;
    }

    conv_kernel<<<B_ * NF, 128>>>(x, convw);
    gn_stats_kernel<<<B_ * GN_G, 256>>>();
    gn_apply_kernel<<<(B_ * NF * T_ + 255) / 256, 256>>>(gamma, beta);

    float* ybuf[3] = { g_bufB, g_bufA, g_bufB };  // device symbol addresses resolved below
    for (int layer = 1; layer <= 3; ++layer) {
        int din = (layer == 1) ? NF : H_;
        dim3 gg(G4H / 128, (B_ * T_) / 128);
        xg_gemm_kernel<<<gg, 256>>>(layer, wih[layer - 1], bb[layer - 1], din);

        float* yptr = nullptr;
        void* sym = nullptr;
        cudaGetSymbolAddress(&sym, (layer == 2) ? g_bufA : g_bufB);
        yptr = (float*)sym;
        void* xgsym = nullptr;
        cudaGetSymbolAddress(&xgsym, g_xg);
        lstm_kernel<<<LNB, LNT, SMEM_BYTES>>>(whh[layer - 1], (const float*)xgsym, yptr);
    }
    (void)ybuf;

    pool_head_kernel<<<B_, H_>>>(headw, headb, (float*)d_out);
}